// round 11
// baseline (speedup 1.0000x reference)
#include <cuda_runtime.h>
#include <cuda_fp16.h>
#include <math.h>

#define N_NODES 200000
#define N_DEST  8192
#define N_EDGE  262144
#define D_MEM   128
#define D_FEAT  128
#define D_EDGE  64
#define D_TIME  32
#define D_MSG   128

// ---------------- scratch (device globals: allocation-free) ------------------
__device__ float g_msg_sum[N_DEST * D_MSG];   // zero-init; dest_kernel re-zeroes
__device__ float g_cnt[N_DEST];
// pre-packed fp16x2 W chunks [chunk][kp][128]:
// 0-7 W_read, 8-14 W_msg, 15-22 W_agg, 23-30 W_upd, 31-34 W_write
__device__ unsigned g_Wf[35 * 2048];

__device__ __forceinline__ int idx_at(const void* p, long long i, int is64) {
    return is64 ? (int)((const long long*)p)[i] : ((const int*)p)[i];
}

// ---------------- fp16 pack / mma ----------------------------------------------
__device__ __forceinline__ unsigned pack_f16(float x0, float x1) {
    unsigned r;
    asm("cvt.rn.f16x2.f32 %0, %1, %2;" : "=r"(r) : "f"(x1), "f"(x0));
    return r;
}

__device__ __forceinline__ void mma_f16(float* c, const unsigned* a, const unsigned* b) {
    asm volatile(
        "mma.sync.aligned.m16n8k16.row.col.f32.f16.f16.f32 "
        "{%0,%1,%2,%3},{%4,%5,%6,%7},{%8,%9},{%0,%1,%2,%3};"
        : "+f"(c[0]), "+f"(c[1]), "+f"(c[2]), "+f"(c[3])
        : "r"(a[0]), "r"(a[1]), "r"(a[2]), "r"(a[3]), "r"(b[0]), "r"(b[1]));
}

// ---------------- cp.async helpers --------------------------------------------
__device__ __forceinline__ void cp16(unsigned dst_smem, const void* src) {
    asm volatile("cp.async.cg.shared.global [%0], [%1], 16;"
                 :: "r"(dst_smem), "l"(src));
}
#define CP_COMMIT() asm volatile("cp.async.commit_group;")
#define CP_WAIT0()  asm volatile("cp.async.wait_group 0;" ::: "memory")

// ---------------- prep: pre-pack ALL weights into fp16x2 ----------------------
__global__ void prep_kernel(const float* __restrict__ W_read,
                            const float* __restrict__ W_msg,
                            const float* __restrict__ W_agg,
                            const float* __restrict__ W_upd,
                            const float* __restrict__ W_write) {
    const int idx = blockIdx.x * blockDim.x + threadIdx.x;
    if (idx >= 35 * 2048) return;
    const int chunk = idx >> 11;
    const int kp = (idx >> 7) & 15;
    const int c = idx & 127;
    const float* W;
    int cl;
    if (chunk < 8)       { W = W_read;  cl = chunk; }
    else if (chunk < 15) { W = W_msg;   cl = chunk - 8; }
    else if (chunk < 23) { W = W_agg;   cl = chunk - 15; }
    else if (chunk < 31) { W = W_upd;   cl = chunk - 23; }
    else                 { W = W_write; cl = chunk - 31; }
    const int row = cl * 32 + 2 * kp;
    g_Wf[idx] = pack_f16(W[row * 128 + c], W[(row + 1) * 128 + c]);
}

// ---------------- shared mma chunk: 1-term fp16, warp tile 32x32 --------------
#define PW 136

__device__ __forceinline__ void mma_k32(const unsigned* __restrict__ Ah, int strideA,
                                        const unsigned* __restrict__ Wh,
                                        int r0, int c0, int gid, int tig,
                                        float acc[2][4][4]) {
#pragma unroll
    for (int half = 0; half < 2; half++) {
        const int kb = half * 8;
        unsigned ah[2][4];
#pragma unroll
        for (int mf = 0; mf < 2; mf++) {
            const int ra = r0 + mf * 16 + gid;
            ah[mf][0] = Ah[ra * strideA + kb + tig];
            ah[mf][1] = Ah[(ra + 8) * strideA + kb + tig];
            ah[mf][2] = Ah[ra * strideA + kb + tig + 4];
            ah[mf][3] = Ah[(ra + 8) * strideA + kb + tig + 4];
        }
#pragma unroll
        for (int nf = 0; nf < 4; nf++) {
            const int col = c0 + nf * 8 + gid;
            unsigned bh[2];
            bh[0] = Wh[(kb + tig) * PW + col];
            bh[1] = Wh[(kb + tig + 4) * PW + col];
#pragma unroll
            for (int mf = 0; mf < 2; mf++) mma_f16(acc[mf][nf], ah[mf], bh);
        }
    }
}

__device__ __forceinline__ void zacc(float acc[2][4][4]) {
#pragma unroll
    for (int m = 0; m < 2; m++)
#pragma unroll
        for (int n = 0; n < 4; n++)
#pragma unroll
            for (int c = 0; c < 4; c++) acc[m][n][c] = 0.f;
}

// ---------------- edge kernel: cp.async pipelined, 64-edge tile ---------------
#define PA 20     // packed A stride
#define PFA 36    // fp32 staging stride
#define PS 116    // stage stride
#define STRIDE_M 132

// smem u32 offsets
#define O_FA0 0        // fp32 A staging buf0: 64*36 = 2304
#define O_FA1 2304     // buf1: 2304
#define O_SA  4608     // packed A: 64*20 = 1280
#define O_WH0 5888     // W buf0: 16*136 = 2176
#define O_WH1 8064     // W buf1: 2176
#define O_ST  10240    // stage: 64*116 = 7424
#define EDGE_U32 17664
#define EDGE_SMEM (EDGE_U32 * 4)   // 70656 B -> 3 CTAs/SM
// msg fp32 buffer aliases [0, 8448) over dead FA/SA/W regions

__device__ __forceinline__ void flush_seg(int d, int tx, const float* r, float rl) {
    float* p = g_msg_sum + (size_t)d * D_MSG + tx * 4;
    atomicAdd(p + 0, r[0]);
    atomicAdd(p + 1, r[1]);
    atomicAdd(p + 2, r[2]);
    atomicAdd(p + 3, r[3]);
    if (tx == 0) atomicAdd(&g_cnt[d], rl);
}

__global__ __launch_bounds__(256, 3) void edge_kernel(
    const float* __restrict__ node_memory, const float* __restrict__ node_features,
    const float* __restrict__ edge_features, const float* __restrict__ time_encoding,
    const void* __restrict__ node_ids,
    const void* __restrict__ source_ids, const void* __restrict__ edge_ids,
    const void* __restrict__ dest_seg,
    const float* __restrict__ b_read, const float* __restrict__ b_msg,
    float* __restrict__ out) {
    extern __shared__ unsigned su[];
    unsigned* sA = su + O_SA;
    unsigned* sSh = su + O_ST;
    __shared__ int s_src[64], s_eid[64], s_dst[64];

    const int tid = threadIdx.x;
    const int lane = tid & 31;
    const int warp = tid >> 5;
    const int gid = lane >> 2;
    const int tig = lane & 3;
    const int r0 = (warp >> 2) * 32;
    const int c0 = (warp & 3) * 32;
    const long long ebase = (long long)blockIdx.x * 64;

    const unsigned* nwid = (const unsigned*)node_ids;
    const int is64 = (nwid[1] == 0u && nwid[3] == 0u);

    if (tid < 64) {
        s_src[tid] = idx_at(source_ids, ebase + tid, is64);
        s_eid[tid] = idx_at(edge_ids, ebase + tid, is64);
        s_dst[tid] = idx_at(dest_seg, ebase + tid, is64);
    }
    __syncthreads();

    const int arow = tid >> 2;
    const int aq = tid & 3;
    const int wkp = tid >> 4;
    const int wc8 = (tid & 15) * 8;

    const unsigned smb = (unsigned)__cvta_generic_to_shared(su);
    const unsigned faB[2] = {smb + O_FA0 * 4, smb + O_FA1 * 4};
    const unsigned whB[2] = {smb + O_WH0 * 4, smb + O_WH1 * 4};
    unsigned* const sWp[2] = {su + O_WH0, su + O_WH1};

    // issue cp.async for chunk kc's A gather (fp32) into staging buf
    auto issueA = [&](int kc, int buf) {
        const float* base = (kc < 4)
            ? node_memory + (size_t)s_src[arow] * D_MEM + kc * 32
            : node_features + (size_t)s_src[arow] * D_FEAT + (kc - 4) * 32;
        const unsigned d = faB[buf] + (arow * PFA + aq * 8) * 4;
        cp16(d, base + aq * 8);
        cp16(d + 16, base + aq * 8 + 4);
    };
    // issue cp.async for global W chunk g into W buf
    auto issueW = [&](int g, int buf) {
        const unsigned* src = g_Wf + g * 2048 + wkp * 128 + wc8;
        const unsigned d = whB[buf] + (wkp * PW + wc8) * 4;
        cp16(d, src);
        cp16(d + 16, src + 4);
    };
    // pack fp32 staging buf -> packed sA
    auto packA = [&](int buf) {
        const float* f = (const float*)(su + (buf ? O_FA1 : O_FA0));
        const float4 v0 = *(const float4*)(f + arow * PFA + aq * 8);
        const float4 v1 = *(const float4*)(f + arow * PFA + aq * 8 + 4);
        *(uint4*)(sA + arow * PA + aq * 4) =
            make_uint4(pack_f16(v0.x, v0.y), pack_f16(v0.z, v0.w),
                       pack_f16(v1.x, v1.y), pack_f16(v1.z, v1.w));
    };

    // prologue: issue chunk 0 (A + W) as one group
    issueA(0, 0);
    issueW(0, 0);
    CP_COMMIT();

    // prefill stage kpairs [64,112): edge feats, time (overlaps group 0 load)
    {
        const float4* ef = (const float4*)(edge_features + (size_t)s_eid[arow] * D_EDGE);
#pragma unroll
        for (int j = 0; j < 4; j++) {
            float4 v = ef[aq * 4 + j];
            const int pi = 64 + aq * 8 + 2 * j;
            sSh[arow * PS + pi] = pack_f16(v.x, v.y);
            sSh[arow * PS + pi + 1] = pack_f16(v.z, v.w);
        }
        const float4* tf = (const float4*)(time_encoding + (ebase + arow) * D_TIME);
#pragma unroll
        for (int j = 0; j < 2; j++) {
            float4 v = tf[aq * 2 + j];
            const int pi = 96 + aq * 4 + 2 * j;
            sSh[arow * PS + pi] = pack_f16(v.x, v.y);
            sSh[arow * PS + pi + 1] = pack_f16(v.z, v.w);
        }
    }

    float acc[2][4][4];
    zacc(acc);

    // ---- Phase 1: src_read, K=256, pipelined ----
    for (int kc = 0; kc < 8; kc++) {
        const int cur = kc & 1, nxt = cur ^ 1;
        CP_WAIT0();          // chunk kc's A+W landed
        __syncthreads();     // all warps done with mma(kc-1); data visible
        if (kc < 7) {
            issueA(kc + 1, nxt);
            issueW(kc + 1, nxt);
        } else {
            issueW(8, nxt);  // phase-2 chunk 0
        }
        CP_COMMIT();
        packA(cur);          // smem->smem convert (cheap)
        __syncthreads();     // sA ready for all warps
        mma_k32(sA, PA, sWp[cur], r0, c0, gid, tig, acc);
    }

    // ---- Phase 1 epilogue: bias+relu -> stage kpairs [0,64) ----
    // (own-acc -> own stage rows; phase-2 first barrier orders cross-warp reads)
#pragma unroll
    for (int mf = 0; mf < 2; mf++) {
        const int ra = r0 + mf * 16 + gid;
#pragma unroll
        for (int nf = 0; nf < 4; nf++) {
            const int col = c0 + nf * 8 + 2 * tig;
            const int pi = col >> 1;
            const float bb0 = b_read[col], bb1 = b_read[col + 1];
            sSh[ra * PS + pi] = pack_f16(fmaxf(acc[mf][nf][0] + bb0, 0.f),
                                         fmaxf(acc[mf][nf][1] + bb1, 0.f));
            sSh[(ra + 8) * PS + pi] = pack_f16(fmaxf(acc[mf][nf][2] + bb0, 0.f),
                                               fmaxf(acc[mf][nf][3] + bb1, 0.f));
        }
    }

    // ---- Phase 2: msgs, K=224, pipelined (one sync per chunk) ----
    zacc(acc);
    for (int kc = 0; kc < 7; kc++) {
        const int cur = (8 + kc) & 1;
        CP_WAIT0();
        __syncthreads();     // orders epilogue writes (kc=0) + mma(kc-1) reads
        if (kc < 6) {
            issueW(9 + kc, cur ^ 1);
            CP_COMMIT();
        }
        mma_k32(sSh + kc * 16, PS, sWp[cur], r0, c0, gid, tig, acc);
    }
    __syncthreads();   // all warps done reading stage/W before msg overwrite

    // ---- Phase 2 epilogue: msgs -> fp32 msg buffer (aliases FA/SA/W) ----
    float* msg = (float*)su;
#pragma unroll
    for (int mf = 0; mf < 2; mf++) {
        const int ra = r0 + mf * 16 + gid;
#pragma unroll
        for (int nf = 0; nf < 4; nf++) {
            const int col = c0 + nf * 8 + 2 * tig;
            const float b0 = b_msg[col], b1 = b_msg[col + 1];
            msg[ra * STRIDE_M + col]           = fmaxf(acc[mf][nf][0] + b0, 0.f);
            msg[ra * STRIDE_M + col + 1]       = fmaxf(acc[mf][nf][1] + b1, 0.f);
            msg[(ra + 8) * STRIDE_M + col]     = fmaxf(acc[mf][nf][2] + b0, 0.f);
            msg[(ra + 8) * STRIDE_M + col + 1] = fmaxf(acc[mf][nf][3] + b1, 0.f);
        }
    }
    __syncthreads();

    // ---- run-coalesced segment-sum atomics (dest_seg globally sorted) ----
    {
        const int tx = lane;
        const int e0 = warp * 8;
        int curd = s_dst[e0];
        float r[4] = {0.f, 0.f, 0.f, 0.f};
        float rl = 0.f;
#pragma unroll
        for (int i = 0; i < 8; i++) {
            const int e = e0 + i;
            const int d = s_dst[e];
            const float4 v = *(const float4*)(msg + e * STRIDE_M + tx * 4);
            if (d != curd) {
                flush_seg(curd, tx, r, rl);
                curd = d;
                r[0] = r[1] = r[2] = r[3] = 0.f;
                rl = 0.f;
            }
            r[0] += v.x; r[1] += v.y; r[2] += v.z; r[3] += v.w;
            rl += 1.f;
        }
        flush_seg(curd, tx, r, rl);
    }

    // ---- node_memory -> out copy slice (rides under compute) ----
    {
        const float4* srcm = (const float4*)node_memory;
        float4* dstm = (float4*)out;
        const long long tot = (long long)N_NODES * D_MEM / 4;
        for (long long i = (long long)blockIdx.x * blockDim.x + tid; i < tot;
             i += (long long)gridDim.x * blockDim.x)
            dstm[i] = srcm[i];
    }
}

// ---------------- dest kernel (proven R10: fp16 MMA, 64-row tile) -------------
#define DPA 20
#define DPS 132
#define DPD 68

#define DO_A 0
#define DO_W 1280
#define DO_S 3456
#define DO_D 11904
#define DEST_U32 16256
#define DEST_SMEM (DEST_U32 * 4)

__global__ __launch_bounds__(256) void dest_kernel(
    const float* __restrict__ node_memory, const float* __restrict__ node_features,
    const void* __restrict__ node_ids,
    const float* __restrict__ b_read, const float* __restrict__ b_agg,
    const float* __restrict__ b_upd, const float* __restrict__ b_write,
    float* __restrict__ out) {
    extern __shared__ unsigned su[];
    unsigned* sA = su + DO_A;
    unsigned* sW = su + DO_W;
    unsigned* sS = su + DO_S;
    unsigned* sD2 = su + DO_D;
    __shared__ int s_nid[64];

    const int tid = threadIdx.x;
    const int lane = tid & 31;
    const int warp = tid >> 5;
    const int gid = lane >> 2;
    const int tig = lane & 3;
    const int r0 = (warp >> 2) * 32;
    const int c0 = (warp & 3) * 32;
    const int rbase = blockIdx.x * 64;

    const unsigned* nwid = (const unsigned*)node_ids;
    const int is64 = (nwid[1] == 0u && nwid[3] == 0u);

    if (tid < 64) s_nid[tid] = idx_at(node_ids, rbase + tid, is64);
    __syncthreads();

    const int arow = tid >> 2;
    const int aq = tid & 3;
    const int wkp = tid >> 4;
    const int wc8 = (tid & 15) * 8;

    float acc[2][4][4];

    // ---- GEMM 1: dst_read, K=256 ----
    zacc(acc);
    for (int kc = 0; kc < 8; kc++) {
        __syncthreads();
        {
            const float* base = (kc < 4)
                ? node_memory + (size_t)s_nid[arow] * D_MEM + kc * 32
                : node_features + (size_t)s_nid[arow] * D_FEAT + (kc - 4) * 32;
            const float4* b4 = (const float4*)base;
            float4 va = b4[aq * 2];
            float4 vb = b4[aq * 2 + 1];
            *(uint4*)(sA + arow * DPA + aq * 4) =
                make_uint4(pack_f16(va.x, va.y), pack_f16(va.z, va.w),
                           pack_f16(vb.x, vb.y), pack_f16(vb.z, vb.w));
        }
        {
            const unsigned* gh = g_Wf + kc * 2048 + wkp * 128 + wc8;
            unsigned* dh = sW + wkp * PW + wc8;
            *(uint4*)dh = *(const uint4*)gh;
            *(uint4*)(dh + 4) = *(const uint4*)(gh + 4);
        }
        __syncthreads();
        mma_k32(sA, DPA, sW, r0, c0, gid, tig, acc);
    }
    __syncthreads();
#pragma unroll
    for (int mf = 0; mf < 2; mf++) {
        const int ra = r0 + mf * 16 + gid;
#pragma unroll
        for (int nf = 0; nf < 4; nf++) {
            const int col = c0 + nf * 8 + 2 * tig;
            const int pi = col >> 1;
            const float bb0 = b_read[col], bb1 = b_read[col + 1];
            unsigned u0 = pack_f16(fmaxf(acc[mf][nf][0] + bb0, 0.f),
                                   fmaxf(acc[mf][nf][1] + bb1, 0.f));
            unsigned u1 = pack_f16(fmaxf(acc[mf][nf][2] + bb0, 0.f),
                                   fmaxf(acc[mf][nf][3] + bb1, 0.f));
            sS[ra * DPS + pi] = u0;       sD2[ra * DPD + pi] = u0;
            sS[(ra + 8) * DPS + pi] = u1; sD2[(ra + 8) * DPD + pi] = u1;
        }
    }

    // msg_mean -> sS kp[64,128); re-zero scratch
    {
        const int dg = rbase + arow;
        const float inv = 1.0f / fmaxf(g_cnt[dg], 1.0f);
        const float4* sp = (const float4*)(g_msg_sum + (size_t)dg * D_MSG + aq * 32);
#pragma unroll
        for (int j4 = 0; j4 < 8; j4++) {
            float4 v = sp[j4];
            const int pi = 64 + aq * 16 + 2 * j4;
            sS[arow * DPS + pi] = pack_f16(v.x * inv, v.y * inv);
            sS[arow * DPS + pi + 1] = pack_f16(v.z * inv, v.w * inv);
        }
        float4 z = {0.f, 0.f, 0.f, 0.f};
        float4* p = (float4*)(g_msg_sum + (size_t)dg * D_MSG + aq * 32);
#pragma unroll
        for (int j4 = 0; j4 < 8; j4++) p[j4] = z;
        if (aq == 0) g_cnt[dg] = 0.f;
    }

    // ---- GEMM 2: agg, K=256 ----
    zacc(acc);
    for (int kc = 0; kc < 8; kc++) {
        __syncthreads();
        {
            const unsigned* gh = g_Wf + (15 + kc) * 2048 + wkp * 128 + wc8;
            unsigned* dh = sW + wkp * PW + wc8;
            *(uint4*)dh = *(const uint4*)gh;
            *(uint4*)(dh + 4) = *(const uint4*)(gh + 4);
        }
        __syncthreads();
        mma_k32(sS + kc * 16, DPS, sW, r0, c0, gid, tig, acc);
    }
    __syncthreads();
#pragma unroll
    for (int mf = 0; mf < 2; mf++) {
        const int ra = r0 + mf * 16 + gid;
#pragma unroll
        for (int nf = 0; nf < 4; nf++) {
            const int col = c0 + nf * 8 + 2 * tig;
            const int pi = col >> 1;
            const float bb0 = b_agg[col], bb1 = b_agg[col + 1];
            sS[ra * DPS + pi] = pack_f16(fmaxf(acc[mf][nf][0] + bb0, 0.f),
                                         fmaxf(acc[mf][nf][1] + bb1, 0.f));
            sS[(ra + 8) * DPS + pi] = pack_f16(fmaxf(acc[mf][nf][2] + bb0, 0.f),
                                               fmaxf(acc[mf][nf][3] + bb1, 0.f));
        }
    }

    // ---- GEMM 3: upd, K=256 (agg from sS, dst_read from sD2) ----
    zacc(acc);
    for (int kc = 0; kc < 8; kc++) {
        __syncthreads();
        {
            const unsigned* gh = g_Wf + (23 + kc) * 2048 + wkp * 128 + wc8;
            unsigned* dh = sW + wkp * PW + wc8;
            *(uint4*)dh = *(const uint4*)gh;
            *(uint4*)(dh + 4) = *(const uint4*)(gh + 4);
        }
        __syncthreads();
        if (kc < 4)
            mma_k32(sS + kc * 16, DPS, sW, r0, c0, gid, tig, acc);
        else
            mma_k32(sD2 + (kc - 4) * 16, DPD, sW, r0, c0, gid, tig, acc);
    }
    __syncthreads();
#pragma unroll
    for (int mf = 0; mf < 2; mf++) {
        const int ra = r0 + mf * 16 + gid;
#pragma unroll
        for (int nf = 0; nf < 4; nf++) {
            const int col = c0 + nf * 8 + 2 * tig;
            const int pi = col >> 1;
            const float bb0 = b_upd[col], bb1 = b_upd[col + 1];
            sS[ra * DPS + pi] = pack_f16(fmaxf(acc[mf][nf][0] + bb0, 0.f),
                                         fmaxf(acc[mf][nf][1] + bb1, 0.f));
            sS[(ra + 8) * DPS + pi] = pack_f16(fmaxf(acc[mf][nf][2] + bb0, 0.f),
                                               fmaxf(acc[mf][nf][3] + bb1, 0.f));
        }
    }

    // ---- GEMM 4: write = tanh(upd @ W_write + b), K=128; scatter ----
    zacc(acc);
    for (int kc = 0; kc < 4; kc++) {
        __syncthreads();
        {
            const unsigned* gh = g_Wf + (31 + kc) * 2048 + wkp * 128 + wc8;
            unsigned* dh = sW + wkp * PW + wc8;
            *(uint4*)dh = *(const uint4*)gh;
            *(uint4*)(dh + 4) = *(const uint4*)(gh + 4);
        }
        __syncthreads();
        mma_k32(sS + kc * 16, DPS, sW, r0, c0, gid, tig, acc);
    }
#pragma unroll
    for (int mf = 0; mf < 2; mf++) {
        const int ra = r0 + mf * 16 + gid;
        const int n0 = s_nid[ra], n1 = s_nid[ra + 8];
#pragma unroll
        for (int nf = 0; nf < 4; nf++) {
            const int col = c0 + nf * 8 + 2 * tig;
            const float bb0 = b_write[col], bb1 = b_write[col + 1];
            float2 o0, o1;
            o0.x = tanhf(acc[mf][nf][0] + bb0);
            o0.y = tanhf(acc[mf][nf][1] + bb1);
            o1.x = tanhf(acc[mf][nf][2] + bb0);
            o1.y = tanhf(acc[mf][nf][3] + bb1);
            *(float2*)(out + (size_t)n0 * D_MEM + col) = o0;
            *(float2*)(out + (size_t)n1 * D_MEM + col) = o1;
        }
    }
}

// ---------------- launch ------------------------------------------------------
extern "C" void kernel_launch(void* const* d_in, const int* in_sizes, int n_in,
                              void* d_out, int out_size) {
    const float* node_memory   = (const float*)d_in[0];
    const float* node_features = (const float*)d_in[1];
    const float* edge_features = (const float*)d_in[2];
    const float* time_encoding = (const float*)d_in[3];
    const void*  node_ids      = d_in[4];
    const void*  source_ids    = d_in[5];
    const void*  edge_ids      = d_in[6];
    const void*  dest_seg      = d_in[7];
    const float* W_read  = (const float*)d_in[8];
    const float* b_read  = (const float*)d_in[9];
    const float* W_msg   = (const float*)d_in[10];
    const float* b_msg   = (const float*)d_in[11];
    const float* W_agg   = (const float*)d_in[12];
    const float* b_agg   = (const float*)d_in[13];
    const float* W_upd   = (const float*)d_in[14];
    const float* b_upd   = (const float*)d_in[15];
    const float* W_write = (const float*)d_in[16];
    const float* b_write = (const float*)d_in[17];
    float* out = (float*)d_out;

    cudaFuncSetAttribute(edge_kernel, cudaFuncAttributeMaxDynamicSharedMemorySize, EDGE_SMEM);
    cudaFuncSetAttribute(dest_kernel, cudaFuncAttributeMaxDynamicSharedMemorySize, DEST_SMEM);

    prep_kernel<<<280, 256>>>(W_read, W_msg, W_agg, W_upd, W_write);

    edge_kernel<<<N_EDGE / 64, 256, EDGE_SMEM>>>(
        node_memory, node_features, edge_features, time_encoding, node_ids,
        source_ids, edge_ids, dest_seg, b_read, b_msg, out);

    dest_kernel<<<N_DEST / 64, 256, DEST_SMEM>>>(
        node_memory, node_features, node_ids,
        b_read, b_agg, b_upd, b_write, out);
}

// round 12
// speedup vs baseline: 1.0077x; 1.0077x over previous
#include <cuda_runtime.h>
#include <cuda_fp16.h>
#include <math.h>

#define N_NODES 200000
#define N_DEST  8192
#define N_EDGE  262144
#define D_MEM   128
#define D_FEAT  128
#define D_EDGE  64
#define D_TIME  32
#define D_MSG   128

// ---------------- scratch (device globals: allocation-free) ------------------
__device__ float g_msg_sum[N_DEST * D_MSG];   // zero-init; dest_kernel re-zeroes
__device__ float g_cnt[N_DEST];
// pre-packed fp16x2 W chunks [chunk][kp][128]:
// 0-7 W_read, 8-14 W_msg, 15-22 W_agg, 23-30 W_upd, 31-34 W_write
__device__ unsigned g_Wf[35 * 2048];

__device__ __forceinline__ int idx_at(const void* p, long long i, int is64) {
    return is64 ? (int)((const long long*)p)[i] : ((const int*)p)[i];
}

// ---------------- fp16 pack / mma ----------------------------------------------
__device__ __forceinline__ unsigned pack_f16(float x0, float x1) {
    unsigned r;
    asm("cvt.rn.f16x2.f32 %0, %1, %2;" : "=r"(r) : "f"(x1), "f"(x0));
    return r;
}

__device__ __forceinline__ void mma_f16(float* c, const unsigned* a, const unsigned* b) {
    asm volatile(
        "mma.sync.aligned.m16n8k16.row.col.f32.f16.f16.f32 "
        "{%0,%1,%2,%3},{%4,%5,%6,%7},{%8,%9},{%0,%1,%2,%3};"
        : "+f"(c[0]), "+f"(c[1]), "+f"(c[2]), "+f"(c[3])
        : "r"(a[0]), "r"(a[1]), "r"(a[2]), "r"(a[3]), "r"(b[0]), "r"(b[1]));
}

// ---------------- cp.async helpers --------------------------------------------
__device__ __forceinline__ void cp16(unsigned dst_smem, const void* src) {
    asm volatile("cp.async.cg.shared.global [%0], [%1], 16;"
                 :: "r"(dst_smem), "l"(src));
}
#define CP_COMMIT() asm volatile("cp.async.commit_group;")
#define CP_WAIT1()  asm volatile("cp.async.wait_group 1;" ::: "memory")

// ---------------- prep: pre-pack ALL weights into fp16x2 ----------------------
__global__ void prep_kernel(const float* __restrict__ W_read,
                            const float* __restrict__ W_msg,
                            const float* __restrict__ W_agg,
                            const float* __restrict__ W_upd,
                            const float* __restrict__ W_write) {
    const int idx = blockIdx.x * blockDim.x + threadIdx.x;
    if (idx >= 35 * 2048) return;
    const int chunk = idx >> 11;
    const int kp = (idx >> 7) & 15;
    const int c = idx & 127;
    const float* W;
    int cl;
    if (chunk < 8)       { W = W_read;  cl = chunk; }
    else if (chunk < 15) { W = W_msg;   cl = chunk - 8; }
    else if (chunk < 23) { W = W_agg;   cl = chunk - 15; }
    else if (chunk < 31) { W = W_upd;   cl = chunk - 23; }
    else                 { W = W_write; cl = chunk - 31; }
    const int row = cl * 32 + 2 * kp;
    g_Wf[idx] = pack_f16(W[row * 128 + c], W[(row + 1) * 128 + c]);
}

// ---------------- shared mma chunk (packed fp16 A), warp tile 32x32 -----------
#define PW 136

__device__ __forceinline__ void mma_k32(const unsigned* __restrict__ Ah, int strideA,
                                        const unsigned* __restrict__ Wh,
                                        int r0, int c0, int gid, int tig,
                                        float acc[2][4][4]) {
#pragma unroll
    for (int half = 0; half < 2; half++) {
        const int kb = half * 8;
        unsigned ah[2][4];
#pragma unroll
        for (int mf = 0; mf < 2; mf++) {
            const int ra = r0 + mf * 16 + gid;
            ah[mf][0] = Ah[ra * strideA + kb + tig];
            ah[mf][1] = Ah[(ra + 8) * strideA + kb + tig];
            ah[mf][2] = Ah[ra * strideA + kb + tig + 4];
            ah[mf][3] = Ah[(ra + 8) * strideA + kb + tig + 4];
        }
#pragma unroll
        for (int nf = 0; nf < 4; nf++) {
            const int col = c0 + nf * 8 + gid;
            unsigned bh[2];
            bh[0] = Wh[(kb + tig) * PW + col];
            bh[1] = Wh[(kb + tig + 4) * PW + col];
#pragma unroll
            for (int mf = 0; mf < 2; mf++) mma_f16(acc[mf][nf], ah[mf], bh);
        }
    }
}

// ---------------- mma chunk with fp32 A (fragments cvt'd on load) -------------
#define PFA 40   // fp32 staging stride: 8*gid+2*tig pattern -> conflict-free LDS.64

__device__ __forceinline__ void mma_k32_f32(const float* __restrict__ A,
                                            const unsigned* __restrict__ Wh,
                                            int r0, int c0, int gid, int tig,
                                            float acc[2][4][4]) {
#pragma unroll
    for (int half = 0; half < 2; half++) {
        const int kf = half * 16 + 2 * tig;
        unsigned ah[2][4];
#pragma unroll
        for (int mf = 0; mf < 2; mf++) {
            const int ra = r0 + mf * 16 + gid;
            const float2 v0 = *(const float2*)(A + ra * PFA + kf);
            const float2 v1 = *(const float2*)(A + (ra + 8) * PFA + kf);
            const float2 v2 = *(const float2*)(A + ra * PFA + kf + 8);
            const float2 v3 = *(const float2*)(A + (ra + 8) * PFA + kf + 8);
            ah[mf][0] = pack_f16(v0.x, v0.y);
            ah[mf][1] = pack_f16(v1.x, v1.y);
            ah[mf][2] = pack_f16(v2.x, v2.y);
            ah[mf][3] = pack_f16(v3.x, v3.y);
        }
        const int kb = half * 8;
#pragma unroll
        for (int nf = 0; nf < 4; nf++) {
            const int col = c0 + nf * 8 + gid;
            unsigned bh[2];
            bh[0] = Wh[(kb + tig) * PW + col];
            bh[1] = Wh[(kb + tig + 4) * PW + col];
#pragma unroll
            for (int mf = 0; mf < 2; mf++) mma_f16(acc[mf][nf], ah[mf], bh);
        }
    }
}

__device__ __forceinline__ void zacc(float acc[2][4][4]) {
#pragma unroll
    for (int m = 0; m < 2; m++)
#pragma unroll
        for (int n = 0; n < 4; n++)
#pragma unroll
            for (int c = 0; c < 4; c++) acc[m][n][c] = 0.f;
}

// ---------------- edge kernel: depth-2 cp.async pipeline ----------------------
#define PS 116
#define STRIDE_M 132

// smem u32 offsets
#define O_FA0 0        // fp32 A staging: 3 x 64*40 = 3 x 2560
#define O_FA1 2560
#define O_FA2 5120
#define O_W0  7680     // W: 3 x 16*136 = 3 x 2176
#define O_W1  9856
#define O_W2  12032
#define O_ST  14208    // stage: 64*116 = 7424
#define EDGE_U32 21632
#define EDGE_SMEM (EDGE_U32 * 4)   // 86528 B -> 2 CTAs/SM
// msg fp32 buffer (64*132 = 8448 u32) aliases staging/W region [0, 14208)

__device__ __forceinline__ void flush_seg(int d, int tx, const float* r, float rl) {
    float* p = g_msg_sum + (size_t)d * D_MSG + tx * 4;
    atomicAdd(p + 0, r[0]);
    atomicAdd(p + 1, r[1]);
    atomicAdd(p + 2, r[2]);
    atomicAdd(p + 3, r[3]);
    if (tx == 0) atomicAdd(&g_cnt[d], rl);
}

__global__ __launch_bounds__(256, 2) void edge_kernel(
    const float* __restrict__ node_memory, const float* __restrict__ node_features,
    const float* __restrict__ edge_features, const float* __restrict__ time_encoding,
    const void* __restrict__ node_ids,
    const void* __restrict__ source_ids, const void* __restrict__ edge_ids,
    const void* __restrict__ dest_seg,
    const float* __restrict__ b_read, const float* __restrict__ b_msg,
    float* __restrict__ out) {
    extern __shared__ unsigned su[];
    const float* fpA[3] = {(const float*)(su + O_FA0), (const float*)(su + O_FA1),
                           (const float*)(su + O_FA2)};
    unsigned* const sWp[3] = {su + O_W0, su + O_W1, su + O_W2};
    unsigned* sSh = su + O_ST;
    __shared__ int s_src[64], s_eid[64], s_dst[64];

    const int tid = threadIdx.x;
    const int lane = tid & 31;
    const int warp = tid >> 5;
    const int gid = lane >> 2;
    const int tig = lane & 3;
    const int r0 = (warp >> 2) * 32;
    const int c0 = (warp & 3) * 32;
    const long long ebase = (long long)blockIdx.x * 64;

    const unsigned* nwid = (const unsigned*)node_ids;
    const int is64 = (nwid[1] == 0u && nwid[3] == 0u);

    if (tid < 64) {
        s_src[tid] = idx_at(source_ids, ebase + tid, is64);
        s_eid[tid] = idx_at(edge_ids, ebase + tid, is64);
        s_dst[tid] = idx_at(dest_seg, ebase + tid, is64);
    }
    __syncthreads();

    const int arow = tid >> 2;
    const int aq = tid & 3;
    const int wkp = tid >> 4;
    const int wc8 = (tid & 15) * 8;

    const unsigned smb = (unsigned)__cvta_generic_to_shared(su);
    const unsigned faB[3] = {smb + O_FA0 * 4, smb + O_FA1 * 4, smb + O_FA2 * 4};
    const unsigned whB[3] = {smb + O_W0 * 4, smb + O_W1 * 4, smb + O_W2 * 4};

    auto issueA = [&](int kc, int slot) {
        const float* base = (kc < 4)
            ? node_memory + (size_t)s_src[arow] * D_MEM + kc * 32
            : node_features + (size_t)s_src[arow] * D_FEAT + (kc - 4) * 32;
        const unsigned d = faB[slot] + (arow * PFA + aq * 8) * 4;
        cp16(d, base + aq * 8);
        cp16(d + 16, base + aq * 8 + 4);
    };
    auto issueW = [&](int gc, int slot) {
        const unsigned* src = g_Wf + gc * 2048 + wkp * 128 + wc8;
        const unsigned d = whB[slot] + (wkp * PW + wc8) * 4;
        cp16(d, src);
        cp16(d + 16, src + 4);
    };

    // prologue: two groups in flight (chunks 0 and 1)
    issueA(0, 0);
    issueW(0, 0);
    CP_COMMIT();
    issueA(1, 1);
    issueW(1, 1);
    CP_COMMIT();

    // prefill stage kpairs [64,112): edge feats, time (overlaps prologue loads)
    {
        const float4* ef = (const float4*)(edge_features + (size_t)s_eid[arow] * D_EDGE);
#pragma unroll
        for (int j = 0; j < 4; j++) {
            float4 v = ef[aq * 4 + j];
            const int pi = 64 + aq * 8 + 2 * j;
            sSh[arow * PS + pi] = pack_f16(v.x, v.y);
            sSh[arow * PS + pi + 1] = pack_f16(v.z, v.w);
        }
        const float4* tf = (const float4*)(time_encoding + (ebase + arow) * D_TIME);
#pragma unroll
        for (int j = 0; j < 2; j++) {
            float4 v = tf[aq * 2 + j];
            const int pi = 96 + aq * 4 + 2 * j;
            sSh[arow * PS + pi] = pack_f16(v.x, v.y);
            sSh[arow * PS + pi + 1] = pack_f16(v.z, v.w);
        }
    }

    float acc[2][4][4];
    zacc(acc);

    // ---- Phase 1: src_read, K=256, depth-2 pipeline, ONE sync per chunk ----
    for (int kc = 0; kc < 8; kc++) {
        CP_WAIT1();          // group kc landed (kc+1 may still be in flight)
        __syncthreads();     // copies visible to all; all warps past mma(kc-1)
        if (kc < 6) {        // issue chunk kc+2 into slot (kc+2)%3 (reader done)
            issueA(kc + 2, (kc + 2) % 3);
            issueW(kc + 2, (kc + 2) % 3);
        } else {             // phase-2 W chunks 8 (kc==6) and 9 (kc==7)
            issueW(kc + 2, (kc + 2) % 3);
        }
        CP_COMMIT();         // exactly one group per iteration
        mma_k32_f32(fpA[kc % 3], sWp[kc % 3], r0, c0, gid, tig, acc);
    }

    // ---- Phase 1 epilogue: bias+relu -> stage kpairs [0,64) ----
#pragma unroll
    for (int mf = 0; mf < 2; mf++) {
        const int ra = r0 + mf * 16 + gid;
#pragma unroll
        for (int nf = 0; nf < 4; nf++) {
            const int col = c0 + nf * 8 + 2 * tig;
            const int pi = col >> 1;
            const float bb0 = b_read[col], bb1 = b_read[col + 1];
            sSh[ra * PS + pi] = pack_f16(fmaxf(acc[mf][nf][0] + bb0, 0.f),
                                         fmaxf(acc[mf][nf][1] + bb1, 0.f));
            sSh[(ra + 8) * PS + pi] = pack_f16(fmaxf(acc[mf][nf][2] + bb0, 0.f),
                                               fmaxf(acc[mf][nf][3] + bb1, 0.f));
        }
    }

    // ---- Phase 2: msgs, K=224, W depth-2, one sync per chunk ----
    zacc(acc);
    for (int kc = 0; kc < 7; kc++) {
        const int gc = 8 + kc;
        CP_WAIT1();          // group gc landed
        __syncthreads();     // stage visible (kc=0); W slot reuse safe
        if (kc < 5) issueW(gc + 2, (gc + 2) % 3);
        CP_COMMIT();         // keep one-group-per-iteration invariant
        mma_k32(sSh + kc * 16, PS, sWp[gc % 3], r0, c0, gid, tig, acc);
    }
    __syncthreads();   // all warps done reading stage/W before msg overwrite

    // ---- Phase 2 epilogue: msgs -> fp32 msg buffer (aliases staging/W) ----
    float* msg = (float*)su;
#pragma unroll
    for (int mf = 0; mf < 2; mf++) {
        const int ra = r0 + mf * 16 + gid;
#pragma unroll
        for (int nf = 0; nf < 4; nf++) {
            const int col = c0 + nf * 8 + 2 * tig;
            const float b0 = b_msg[col], b1 = b_msg[col + 1];
            msg[ra * STRIDE_M + col]           = fmaxf(acc[mf][nf][0] + b0, 0.f);
            msg[ra * STRIDE_M + col + 1]       = fmaxf(acc[mf][nf][1] + b1, 0.f);
            msg[(ra + 8) * STRIDE_M + col]     = fmaxf(acc[mf][nf][2] + b0, 0.f);
            msg[(ra + 8) * STRIDE_M + col + 1] = fmaxf(acc[mf][nf][3] + b1, 0.f);
        }
    }
    __syncthreads();

    // ---- run-coalesced segment-sum atomics (dest_seg globally sorted) ----
    {
        const int tx = lane;
        const int e0 = warp * 8;
        int curd = s_dst[e0];
        float r[4] = {0.f, 0.f, 0.f, 0.f};
        float rl = 0.f;
#pragma unroll
        for (int i = 0; i < 8; i++) {
            const int e = e0 + i;
            const int d = s_dst[e];
            const float4 v = *(const float4*)(msg + e * STRIDE_M + tx * 4);
            if (d != curd) {
                flush_seg(curd, tx, r, rl);
                curd = d;
                r[0] = r[1] = r[2] = r[3] = 0.f;
                rl = 0.f;
            }
            r[0] += v.x; r[1] += v.y; r[2] += v.z; r[3] += v.w;
            rl += 1.f;
        }
        flush_seg(curd, tx, r, rl);
    }

    // ---- node_memory -> out copy slice (rides under compute) ----
    {
        const float4* srcm = (const float4*)node_memory;
        float4* dstm = (float4*)out;
        const long long tot = (long long)N_NODES * D_MEM / 4;
        for (long long i = (long long)blockIdx.x * blockDim.x + tid; i < tot;
             i += (long long)gridDim.x * blockDim.x)
            dstm[i] = srcm[i];
    }
}

// ---------------- dest kernel (proven R10: fp16 MMA, 64-row tile) -------------
#define DPA 20
#define DPS 132
#define DPD 68

#define DO_A 0
#define DO_W 1280
#define DO_S 3456
#define DO_D 11904
#define DEST_U32 16256
#define DEST_SMEM (DEST_U32 * 4)

__global__ __launch_bounds__(256) void dest_kernel(
    const float* __restrict__ node_memory, const float* __restrict__ node_features,
    const void* __restrict__ node_ids,
    const float* __restrict__ b_read, const float* __restrict__ b_agg,
    const float* __restrict__ b_upd, const float* __restrict__ b_write,
    float* __restrict__ out) {
    extern __shared__ unsigned su[];
    unsigned* sA = su + DO_A;
    unsigned* sW = su + DO_W;
    unsigned* sS = su + DO_S;
    unsigned* sD2 = su + DO_D;
    __shared__ int s_nid[64];

    const int tid = threadIdx.x;
    const int lane = tid & 31;
    const int warp = tid >> 5;
    const int gid = lane >> 2;
    const int tig = lane & 3;
    const int r0 = (warp >> 2) * 32;
    const int c0 = (warp & 3) * 32;
    const int rbase = blockIdx.x * 64;

    const unsigned* nwid = (const unsigned*)node_ids;
    const int is64 = (nwid[1] == 0u && nwid[3] == 0u);

    if (tid < 64) s_nid[tid] = idx_at(node_ids, rbase + tid, is64);
    __syncthreads();

    const int arow = tid >> 2;
    const int aq = tid & 3;
    const int wkp = tid >> 4;
    const int wc8 = (tid & 15) * 8;

    float acc[2][4][4];

    // ---- GEMM 1: dst_read, K=256 ----
    zacc(acc);
    for (int kc = 0; kc < 8; kc++) {
        __syncthreads();
        {
            const float* base = (kc < 4)
                ? node_memory + (size_t)s_nid[arow] * D_MEM + kc * 32
                : node_features + (size_t)s_nid[arow] * D_FEAT + (kc - 4) * 32;
            const float4* b4 = (const float4*)base;
            float4 va = b4[aq * 2];
            float4 vb = b4[aq * 2 + 1];
            *(uint4*)(sA + arow * DPA + aq * 4) =
                make_uint4(pack_f16(va.x, va.y), pack_f16(va.z, va.w),
                           pack_f16(vb.x, vb.y), pack_f16(vb.z, vb.w));
        }
        {
            const unsigned* gh = g_Wf + kc * 2048 + wkp * 128 + wc8;
            unsigned* dh = sW + wkp * PW + wc8;
            *(uint4*)dh = *(const uint4*)gh;
            *(uint4*)(dh + 4) = *(const uint4*)(gh + 4);
        }
        __syncthreads();
        mma_k32(sA, DPA, sW, r0, c0, gid, tig, acc);
    }
    __syncthreads();
#pragma unroll
    for (int mf = 0; mf < 2; mf++) {
        const int ra = r0 + mf * 16 + gid;
#pragma unroll
        for (int nf = 0; nf < 4; nf++) {
            const int col = c0 + nf * 8 + 2 * tig;
            const int pi = col >> 1;
            const float bb0 = b_read[col], bb1 = b_read[col + 1];
            unsigned u0 = pack_f16(fmaxf(acc[mf][nf][0] + bb0, 0.f),
                                   fmaxf(acc[mf][nf][1] + bb1, 0.f));
            unsigned u1 = pack_f16(fmaxf(acc[mf][nf][2] + bb0, 0.f),
                                   fmaxf(acc[mf][nf][3] + bb1, 0.f));
            sS[ra * DPS + pi] = u0;       sD2[ra * DPD + pi] = u0;
            sS[(ra + 8) * DPS + pi] = u1; sD2[(ra + 8) * DPD + pi] = u1;
        }
    }

    // msg_mean -> sS kp[64,128); re-zero scratch
    {
        const int dg = rbase + arow;
        const float inv = 1.0f / fmaxf(g_cnt[dg], 1.0f);
        const float4* sp = (const float4*)(g_msg_sum + (size_t)dg * D_MSG + aq * 32);
#pragma unroll
        for (int j4 = 0; j4 < 8; j4++) {
            float4 v = sp[j4];
            const int pi = 64 + aq * 16 + 2 * j4;
            sS[arow * DPS + pi] = pack_f16(v.x * inv, v.y * inv);
            sS[arow * DPS + pi + 1] = pack_f16(v.z * inv, v.w * inv);
        }
        float4 z = {0.f, 0.f, 0.f, 0.f};
        float4* p = (float4*)(g_msg_sum + (size_t)dg * D_MSG + aq * 32);
#pragma unroll
        for (int j4 = 0; j4 < 8; j4++) p[j4] = z;
        if (aq == 0) g_cnt[dg] = 0.f;
    }

    // ---- GEMM 2: agg, K=256 ----
    zacc(acc);
    for (int kc = 0; kc < 8; kc++) {
        __syncthreads();
        {
            const unsigned* gh = g_Wf + (15 + kc) * 2048 + wkp * 128 + wc8;
            unsigned* dh = sW + wkp * PW + wc8;
            *(uint4*)dh = *(const uint4*)gh;
            *(uint4*)(dh + 4) = *(const uint4*)(gh + 4);
        }
        __syncthreads();
        mma_k32(sS + kc * 16, DPS, sW, r0, c0, gid, tig, acc);
    }
    __syncthreads();
#pragma unroll
    for (int mf = 0; mf < 2; mf++) {
        const int ra = r0 + mf * 16 + gid;
#pragma unroll
        for (int nf = 0; nf < 4; nf++) {
            const int col = c0 + nf * 8 + 2 * tig;
            const int pi = col >> 1;
            const float bb0 = b_agg[col], bb1 = b_agg[col + 1];
            sS[ra * DPS + pi] = pack_f16(fmaxf(acc[mf][nf][0] + bb0, 0.f),
                                         fmaxf(acc[mf][nf][1] + bb1, 0.f));
            sS[(ra + 8) * DPS + pi] = pack_f16(fmaxf(acc[mf][nf][2] + bb0, 0.f),
                                               fmaxf(acc[mf][nf][3] + bb1, 0.f));
        }
    }

    // ---- GEMM 3: upd, K=256 (agg from sS, dst_read from sD2) ----
    zacc(acc);
    for (int kc = 0; kc < 8; kc++) {
        __syncthreads();
        {
            const unsigned* gh = g_Wf + (23 + kc) * 2048 + wkp * 128 + wc8;
            unsigned* dh = sW + wkp * PW + wc8;
            *(uint4*)dh = *(const uint4*)gh;
            *(uint4*)(dh + 4) = *(const uint4*)(gh + 4);
        }
        __syncthreads();
        if (kc < 4)
            mma_k32(sS + kc * 16, DPS, sW, r0, c0, gid, tig, acc);
        else
            mma_k32(sD2 + (kc - 4) * 16, DPD, sW, r0, c0, gid, tig, acc);
    }
    __syncthreads();
#pragma unroll
    for (int mf = 0; mf < 2; mf++) {
        const int ra = r0 + mf * 16 + gid;
#pragma unroll
        for (int nf = 0; nf < 4; nf++) {
            const int col = c0 + nf * 8 + 2 * tig;
            const int pi = col >> 1;
            const float bb0 = b_upd[col], bb1 = b_upd[col + 1];
            sS[ra * DPS + pi] = pack_f16(fmaxf(acc[mf][nf][0] + bb0, 0.f),
                                         fmaxf(acc[mf][nf][1] + bb1, 0.f));
            sS[(ra + 8) * DPS + pi] = pack_f16(fmaxf(acc[mf][nf][2] + bb0, 0.f),
                                               fmaxf(acc[mf][nf][3] + bb1, 0.f));
        }
    }

    // ---- GEMM 4: write = tanh(upd @ W_write + b), K=128; scatter ----
    zacc(acc);
    for (int kc = 0; kc < 4; kc++) {
        __syncthreads();
        {
            const unsigned* gh = g_Wf + (31 + kc) * 2048 + wkp * 128 + wc8;
            unsigned* dh = sW + wkp * PW + wc8;
            *(uint4*)dh = *(const uint4*)gh;
            *(uint4*)(dh + 4) = *(const uint4*)(gh + 4);
        }
        __syncthreads();
        mma_k32(sS + kc * 16, DPS, sW, r0, c0, gid, tig, acc);
    }
#pragma unroll
    for (int mf = 0; mf < 2; mf++) {
        const int ra = r0 + mf * 16 + gid;
        const int n0 = s_nid[ra], n1 = s_nid[ra + 8];
#pragma unroll
        for (int nf = 0; nf < 4; nf++) {
            const int col = c0 + nf * 8 + 2 * tig;
            const float bb0 = b_write[col], bb1 = b_write[col + 1];
            float2 o0, o1;
            o0.x = tanhf(acc[mf][nf][0] + bb0);
            o0.y = tanhf(acc[mf][nf][1] + bb1);
            o1.x = tanhf(acc[mf][nf][2] + bb0);
            o1.y = tanhf(acc[mf][nf][3] + bb1);
            *(float2*)(out + (size_t)n0 * D_MEM + col) = o0;
            *(float2*)(out + (size_t)n1 * D_MEM + col) = o1;
        }
    }
}

// ---------------- launch ------------------------------------------------------
extern "C" void kernel_launch(void* const* d_in, const int* in_sizes, int n_in,
                              void* d_out, int out_size) {
    const float* node_memory   = (const float*)d_in[0];
    const float* node_features = (const float*)d_in[1];
    const float* edge_features = (const float*)d_in[2];
    const float* time_encoding = (const float*)d_in[3];
    const void*  node_ids      = d_in[4];
    const void*  source_ids    = d_in[5];
    const void*  edge_ids      = d_in[6];
    const void*  dest_seg      = d_in[7];
    const float* W_read  = (const float*)d_in[8];
    const float* b_read  = (const float*)d_in[9];
    const float* W_msg   = (const float*)d_in[10];
    const float* b_msg   = (const float*)d_in[11];
    const float* W_agg   = (const float*)d_in[12];
    const float* b_agg   = (const float*)d_in[13];
    const float* W_upd   = (const float*)d_in[14];
    const float* b_upd   = (const float*)d_in[15];
    const float* W_write = (const float*)d_in[16];
    const float* b_write = (const float*)d_in[17];
    float* out = (float*)d_out;

    cudaFuncSetAttribute(edge_kernel, cudaFuncAttributeMaxDynamicSharedMemorySize, EDGE_SMEM);
    cudaFuncSetAttribute(dest_kernel, cudaFuncAttributeMaxDynamicSharedMemorySize, DEST_SMEM);

    prep_kernel<<<280, 256>>>(W_read, W_msg, W_agg, W_upd, W_write);

    edge_kernel<<<N_EDGE / 64, 256, EDGE_SMEM>>>(
        node_memory, node_features, edge_features, time_encoding, node_ids,
        source_ids, edge_ids, dest_seg, b_read, b_msg, out);

    dest_kernel<<<N_DEST / 64, 256, DEST_SMEM>>>(
        node_memory, node_features, node_ids,
        b_read, b_agg, b_upd, b_write, out);
}